// round 1
// baseline (speedup 1.0000x reference)
#include <cuda_runtime.h>
#include <cuda_bf16.h>
#include <math.h>

#define NB     32
#define NEV    393216
#define NSEG   48
#define SEGLEN 8192
#define WID    320
#define HEI    240
#define HW     76800
#define NWORD  2400        // HW/32
#define SIDX_C 4
#define EIDX_C 38
#define ROWS_USED 34       // rows 4..37
#define NSTEP  33          // rows 5..37

// ---------------- device scratch (static: no allocation allowed) ----------------
__device__ int           g_mom[NB * NSEG * 10];             // m1x,hx0,hx1,hx318,hx319, m1y,hy0,hy1,hy238,hy239
__device__ unsigned      g_packed[(size_t)NB * ROWS_USED * SEGLEN]; // (y<<9)|x
__device__ int           g_aligned[NB * NSEG * 2];          // [b][s][{ax,ay}]
__device__ unsigned char g_flags[NB * NSTEP];
__device__ int           g_cont[(size_t)NB * HW];
__device__ int           g_conf[(size_t)NB * HW];

// ---------------- K1: per-segment histogram moments + packed coords ----------------
__global__ void __launch_bounds__(256) k_hist(const int* __restrict__ ev) {
    __shared__ int shx[WID];
    __shared__ int shy[HEI];
    __shared__ int sm1x, sm1y;
    int bx = blockIdx.x;
    int b = bx / NSEG, s = bx % NSEG;
    int t = threadIdx.x;

    for (int e = t; e < WID; e += 256) shx[e] = 0;
    for (int e = t; e < HEI; e += 256) shy[e] = 0;
    if (t == 0) { sm1x = 0; sm1y = 0; }
    __syncthreads();

    const int* base = ev + ((size_t)b * NEV + (size_t)s * SEGLEN) * 5;
    bool wr = (s >= SIDX_C && s < EIDX_C);
    int sp = s - SIDX_C; if (sp < 0) sp = 0;
    unsigned* pk = g_packed + ((size_t)b * ROWS_USED + sp) * SEGLEN;

    for (int e = t; e < SEGLEN; e += 256) {
        int x = base[(size_t)e * 5];
        int y = base[(size_t)e * 5 + 1];
        x = min(max(x, 0), WID - 1);
        y = min(max(y, 0), HEI - 1);
        atomicAdd(&shx[x], 1);
        atomicAdd(&shy[y], 1);
        if (wr) pk[e] = (unsigned)((y << 9) | x);
    }
    __syncthreads();

    int l1 = 0, l2 = 0;
    for (int e = t; e < WID; e += 256) l1 += e * shx[e];
    for (int e = t; e < HEI; e += 256) l2 += e * shy[e];
    for (int o = 16; o; o >>= 1) {
        l1 += __shfl_down_sync(0xffffffffu, l1, o);
        l2 += __shfl_down_sync(0xffffffffu, l2, o);
    }
    if ((t & 31) == 0) { atomicAdd(&sm1x, l1); atomicAdd(&sm1y, l2); }
    __syncthreads();

    if (t == 0) {
        int* mm = g_mom + (b * NSEG + s) * 10;
        mm[0] = sm1x; mm[1] = shx[0]; mm[2] = shx[1]; mm[3] = shx[WID - 2]; mm[4] = shx[WID - 1];
        mm[5] = sm1y; mm[6] = shy[0]; mm[7] = shy[1]; mm[8] = shy[HEI - 2]; mm[9] = shy[HEI - 1];
    }
}

// ---------------- K2: means (blur collapsed to moments), aligned, outlier flags ----------------
__device__ __forceinline__ void sort10(float* a) {
    #pragma unroll
    for (int i = 1; i < 10; i++) {
        float v = a[i]; int j = i - 1;
        while (j >= 0 && a[j] > v) { a[j + 1] = a[j]; j--; }
        a[j + 1] = v;
    }
}

__device__ bool outl(const float* m, int i) {
    float w[10], s[10];
    #pragma unroll
    for (int t = 0; t < 10; t++) { w[t] = m[i + t]; s[t] = w[t]; }
    sort10(s);
    float med = 0.5f * (s[4] + s[5]);
    float d0 = fabsf(w[0] - med);
    float ds[10];
    #pragma unroll
    for (int t = 0; t < 10; t++) ds[t] = fabsf(w[t] - med);
    sort10(ds);
    float mad = 0.5f * (ds[4] + ds[5]);
    float mz = (0.6745f * d0) / mad;   // mad==0 -> inf/nan, IEEE matches jnp
    return mz > 3.0f;
}

__global__ void __launch_bounds__(128) k_mean(const float* __restrict__ kern) {
    __shared__ float skk[25];
    __shared__ float smX[NSEG], smY[NSEG];
    int b = blockIdx.x, t = threadIdx.x;
    if (t < 25) skk[t] = kern[t];
    __syncthreads();

    if (t < 96) {
        int coord = t / NSEG, s = t % NSEG;
        int D = coord ? HEI : WID;
        double num = 0.0;
        #pragma unroll
        for (int a = -2; a <= 2; a++) {
            int si = s + a;
            if (si < 0 || si >= NSEG) continue;
            const int* mm = g_mom + (b * NSEG + si) * 10 + coord * 5;
            double m1  = (double)mm[0];
            double h0  = (double)mm[1];
            double h1  = (double)mm[2];
            double hD2 = (double)mm[3];
            double hD1 = (double)mm[4];
            double kr0 = skk[(a + 2) * 5 + 0];
            double kr1 = skk[(a + 2) * 5 + 1];
            double kr2 = skk[(a + 2) * 5 + 2];
            double kr3 = skk[(a + 2) * 5 + 3];
            double kr4 = skk[(a + 2) * 5 + 4];
            double Ka = kr0 + kr1 + kr2 + kr3 + kr4;
            double Sb = -2.0 * kr0 - kr1 + kr3 + 2.0 * kr4;
            num += Ka * m1 - Sb * (double)SEGLEN
                 + h0 * (kr3 + 2.0 * kr4) + h1 * kr4
                 - hD1 * ((double)D * kr1 + (double)(D + 1) * kr0)
                 - hD2 * ((double)D * kr0);
        }
        float mean = (float)(num / (double)SEGLEN);
        if (coord) smY[s] = mean; else smX[s] = mean;
    }
    __syncthreads();

    if (t < 96) {
        int coord = t / NSEG, s = t % NSEG;
        int D = coord ? HEI : WID;
        const float* m = coord ? smY : smX;
        float start = m[SIDX_C];
        float dis = (float)(D / 2) - start;
        float a = rintf((m[s] - start) - dis);     // round half-to-even like jnp.round
        g_aligned[(b * NSEG + s) * 2 + coord] = (int)a;
    }
    if (t < NSTEP) {
        bool fx = outl(smX, SIDX_C + 1 + t);
        bool fy = outl(smY, SIDX_C + 1 + t);
        g_flags[b * NSTEP + t] = (fx || fy) ? 1 : 0;
    }
}

// ---------------- K4: sequential scan per batch + fused normalize ----------------
__global__ void __launch_bounds__(1024) k_scan(float* __restrict__ out) {
    __shared__ unsigned v0[NWORD], v1[NWORD], vraw[NWORD];
    __shared__ int s_red;
    __shared__ double s_sum, s_sq;

    int b = blockIdx.x, t = threadIdx.x;
    int* cont = g_cont + (size_t)b * HW;
    int* conf = g_conf + (size_t)b * HW;

    for (int p = t; p < HW; p += 1024) { cont[p] = 0; conf[p] = 0; }
    for (int w = t; w < NWORD; w += 1024) { v0[w] = 0u; v1[w] = 0xffffffffu; }
    if (t == 0) s_red = 0;
    __syncthreads();

    // row SIDX: init container + v0
    {
        const unsigned* pr = g_packed + (size_t)b * ROWS_USED * SEGLEN;
        int ax = g_aligned[(b * NSEG + SIDX_C) * 2];
        int ay = g_aligned[(b * NSEG + SIDX_C) * 2 + 1];
        for (int e = t; e < SEGLEN; e += 1024) {
            unsigned pkv = pr[e];
            int x = (int)(pkv & 511u), y = (int)(pkv >> 9);
            int xx = min(max(x - ax, 0), WID - 1);
            int yy = min(max(y - ay, 0), HEI - 1);
            int p = yy * WID + xx;
            atomicAdd(&cont[p], 1);
            atomicOr(&v0[p >> 5], 1u << (p & 31));
        }
    }
    __syncthreads();

    int lc = 0;
    for (int w = t; w < NWORD; w += 1024) lc += __popc(v0[w]);
    for (int o = 16; o; o >>= 1) lc += __shfl_down_sync(0xffffffffu, lc, o);
    if ((t & 31) == 0) atomicAdd(&s_red, lc);
    __syncthreads();
    int cnt_v0 = s_red;

    for (int r = SIDX_C + 1; r < EIDX_C; r++) {
        if (g_flags[b * NSTEP + (r - SIDX_C - 1)]) continue;   // inactive row: no state change
        if (t == 0) s_red = 0;
        for (int w = t; w < NWORD; w += 1024) vraw[w] = 0u;
        __syncthreads();

        const unsigned* pr = g_packed + ((size_t)b * ROWS_USED + (r - SIDX_C)) * SEGLEN;
        int ax = g_aligned[(b * NSEG + r) * 2];
        int ay = g_aligned[(b * NSEG + r) * 2 + 1];
        int pl[8];
        #pragma unroll
        for (int k = 0; k < 8; k++) {
            int e = t + k * 1024;
            unsigned pkv = pr[e];
            int x = (int)(pkv & 511u), y = (int)(pkv >> 9);
            int xx = min(max(x - ax, 0), WID - 1);
            int yy = min(max(y - ay, 0), HEI - 1);
            int p = yy * WID + xx;
            pl[k] = p;
            atomicOr(&vraw[p >> 5], 1u << (p & 31));
        }
        __syncthreads();

        int ln = 0;
        for (int w = t; w < NWORD; w += 1024) {
            unsigned raw = vraw[w];
            unsigned o0 = v0[w];
            ln += __popc(raw & ~o0);
            unsigned cm = raw & o0 & v1[w];   // conf update (gated only by 'active', true here)
            while (cm) {
                int bit = __ffs(cm) - 1;
                conf[w * 32 + bit] += 1;       // single writer per word: no atomic needed
                cm &= cm - 1;
            }
        }
        for (int o = 16; o; o >>= 1) ln += __shfl_down_sync(0xffffffffu, ln, o);
        if ((t & 31) == 0) atomicAdd(&s_red, ln);
        __syncthreads();

        int newc = s_red;
        float ratio = (float)newc / (float)(cnt_v0 + newc);   // exact-int fp32 division, matches jnp
        if (ratio < 0.01f) break;   // stopped: all later steps are provably no-ops

        for (int w = t; w < NWORD; w += 1024) {
            unsigned o0 = v0[w];
            v1[w] = o0;
            v0[w] = o0 | vraw[w];
        }
        #pragma unroll
        for (int k = 0; k < 8; k++) atomicAdd(&cont[pl[k]], 1);
        cnt_v0 += newc;
        __syncthreads();
    }

    // ------- fused normalize: clamp = mean + 3*std(ddof=1), clip/scale -------
    __syncthreads();
    for (int pass = 0; pass < 2; pass++) {
        int* src = pass ? conf : cont;
        if (t == 0) { s_sum = 0.0; s_sq = 0.0; }
        __syncthreads();
        double ls = 0.0, lq = 0.0;
        for (int p = t; p < HW; p += 1024) {
            double v = (double)src[p];
            ls += v; lq += v * v;
        }
        for (int o = 16; o; o >>= 1) {
            ls += __shfl_down_sync(0xffffffffu, ls, o);
            lq += __shfl_down_sync(0xffffffffu, lq, o);
        }
        if ((t & 31) == 0) { atomicAdd(&s_sum, ls); atomicAdd(&s_sq, lq); }
        __syncthreads();
        double n = (double)HW;
        double mu = s_sum / n;
        double var = (s_sq - s_sum * s_sum / n) / (n - 1.0);
        if (var < 0.0) var = 0.0;
        float clampv = (float)(mu + 3.0 * sqrt(var));
        float* op = out + ((size_t)b * 2 + pass) * HW;
        for (int p = t; p < HW; p += 1024) {
            float v = (float)src[p];
            op[p] = fminf(v, clampv) / clampv;   // v>=0; clamp==0 -> 0/0=nan like ref
        }
        __syncthreads();
    }
}

// ---------------- launch ----------------
extern "C" void kernel_launch(void* const* d_in, const int* in_sizes, int n_in,
                              void* d_out, int out_size) {
    const int*   ev   = (const int*)d_in[0];
    const float* kern = (const float*)d_in[1];
    float*       out  = (float*)d_out;
    (void)in_sizes; (void)n_in; (void)out_size;

    k_hist<<<NB * NSEG, 256>>>(ev);
    k_mean<<<NB, 128>>>(kern);
    k_scan<<<NB, 1024>>>(out);
}

// round 2
// speedup vs baseline: 1.8860x; 1.8860x over previous
#include <cuda_runtime.h>
#include <cuda_bf16.h>
#include <math.h>

#define NB     32
#define NEV    393216
#define NSEG   48
#define SEGLEN 8192
#define WID    320
#define HEI    240
#define HW     76800
#define NWORD  2400        // HW/32
#define SIDX_C 4
#define EIDX_C 38
#define ROWS_USED 34       // rows 4..37 (row index 0..33)
#define NSTEP  33          // steps = rows 1..33

// ---------------- device scratch ----------------
__device__ int           g_mom[NB * NSEG * 10];
__device__ unsigned      g_packed[(size_t)NB * ROWS_USED * SEGLEN]; // (y<<9)|x
__device__ int           g_aligned[NB * NSEG * 2];
__device__ unsigned char g_flags[NB * NSTEP];
__device__ unsigned      g_raw[(size_t)NB * ROWS_USED * NWORD];     // per-row bitmaps
__device__ unsigned char g_applied[NB * ROWS_USED];
__device__ int           g_cont[(size_t)NB * HW];
__device__ int           g_conf[(size_t)NB * HW];

// ---------------- K1: per-segment histogram moments + packed coords (uint4) ----------------
__global__ void __launch_bounds__(256) k_hist(const int* __restrict__ ev) {
    __shared__ int shx[WID];
    __shared__ int shy[HEI];
    __shared__ int sm1x, sm1y;
    int bx = blockIdx.x;
    int b = bx / NSEG, s = bx % NSEG;
    int t = threadIdx.x;

    for (int e = t; e < WID; e += 256) shx[e] = 0;
    for (int e = t; e < HEI; e += 256) shy[e] = 0;
    if (t == 0) { sm1x = 0; sm1y = 0; }
    __syncthreads();

    const uint4* evv = (const uint4*)(ev + ((size_t)b * NEV + (size_t)s * SEGLEN) * 5);
    bool wr = (s >= SIDX_C && s < EIDX_C);
    int sp = s - SIDX_C; if (sp < 0) sp = 0;
    uint4* pk4 = (uint4*)(g_packed + ((size_t)b * ROWS_USED + sp) * SEGLEN);

    // 8192 events = 10240 uint4; group of 5 uint4 = 4 events
    for (int g = t; g < SEGLEN / 4; g += 256) {
        uint4 a0 = evv[g * 5 + 0];
        uint4 a1 = evv[g * 5 + 1];
        uint4 a2 = evv[g * 5 + 2];
        uint4 a3 = evv[g * 5 + 3];
        uint4 a4 = evv[g * 5 + 4];
        int x0 = (int)a0.x, y0 = (int)a0.y;
        int x1 = (int)a1.y, y1 = (int)a1.z;
        int x2 = (int)a2.z, y2 = (int)a2.w;
        int x3 = (int)a3.w, y3 = (int)a4.x;
        atomicAdd(&shx[x0], 1); atomicAdd(&shy[y0], 1);
        atomicAdd(&shx[x1], 1); atomicAdd(&shy[y1], 1);
        atomicAdd(&shx[x2], 1); atomicAdd(&shy[y2], 1);
        atomicAdd(&shx[x3], 1); atomicAdd(&shy[y3], 1);
        if (wr) {
            uint4 p;
            p.x = (unsigned)((y0 << 9) | x0);
            p.y = (unsigned)((y1 << 9) | x1);
            p.z = (unsigned)((y2 << 9) | x2);
            p.w = (unsigned)((y3 << 9) | x3);
            pk4[g] = p;
        }
    }
    __syncthreads();

    int l1 = 0, l2 = 0;
    for (int e = t; e < WID; e += 256) l1 += e * shx[e];
    for (int e = t; e < HEI; e += 256) l2 += e * shy[e];
    for (int o = 16; o; o >>= 1) {
        l1 += __shfl_down_sync(0xffffffffu, l1, o);
        l2 += __shfl_down_sync(0xffffffffu, l2, o);
    }
    if ((t & 31) == 0) { atomicAdd(&sm1x, l1); atomicAdd(&sm1y, l2); }
    __syncthreads();

    if (t == 0) {
        int* mm = g_mom + (b * NSEG + s) * 10;
        mm[0] = sm1x; mm[1] = shx[0]; mm[2] = shx[1]; mm[3] = shx[WID - 2]; mm[4] = shx[WID - 1];
        mm[5] = sm1y; mm[6] = shy[0]; mm[7] = shy[1]; mm[8] = shy[HEI - 2]; mm[9] = shy[HEI - 1];
    }
}

// ---------------- K2: means + aligned + outlier flags ----------------
__device__ __forceinline__ void sort10(float* a) {
    #pragma unroll
    for (int i = 1; i < 10; i++) {
        float v = a[i]; int j = i - 1;
        while (j >= 0 && a[j] > v) { a[j + 1] = a[j]; j--; }
        a[j + 1] = v;
    }
}

__device__ bool outl(const float* m, int i) {
    float w[10], s[10];
    #pragma unroll
    for (int t = 0; t < 10; t++) { w[t] = m[i + t]; s[t] = w[t]; }
    sort10(s);
    float med = 0.5f * (s[4] + s[5]);
    float d0 = fabsf(w[0] - med);
    float ds[10];
    #pragma unroll
    for (int t = 0; t < 10; t++) ds[t] = fabsf(w[t] - med);
    sort10(ds);
    float mad = 0.5f * (ds[4] + ds[5]);
    float mz = (0.6745f * d0) / mad;
    return mz > 3.0f;
}

__global__ void __launch_bounds__(128) k_mean(const float* __restrict__ kern) {
    __shared__ float skk[25];
    __shared__ float smX[NSEG], smY[NSEG];
    int b = blockIdx.x, t = threadIdx.x;
    if (t < 25) skk[t] = kern[t];
    __syncthreads();

    if (t < 96) {
        int coord = t / NSEG, s = t % NSEG;
        int D = coord ? HEI : WID;
        double num = 0.0;
        #pragma unroll
        for (int a = -2; a <= 2; a++) {
            int si = s + a;
            if (si < 0 || si >= NSEG) continue;
            const int* mm = g_mom + (b * NSEG + si) * 10 + coord * 5;
            double m1  = (double)mm[0];
            double h0  = (double)mm[1];
            double h1  = (double)mm[2];
            double hD2 = (double)mm[3];
            double hD1 = (double)mm[4];
            double kr0 = skk[(a + 2) * 5 + 0];
            double kr1 = skk[(a + 2) * 5 + 1];
            double kr2 = skk[(a + 2) * 5 + 2];
            double kr3 = skk[(a + 2) * 5 + 3];
            double kr4 = skk[(a + 2) * 5 + 4];
            double Ka = kr0 + kr1 + kr2 + kr3 + kr4;
            double Sb = -2.0 * kr0 - kr1 + kr3 + 2.0 * kr4;
            num += Ka * m1 - Sb * (double)SEGLEN
                 + h0 * (kr3 + 2.0 * kr4) + h1 * kr4
                 - hD1 * ((double)D * kr1 + (double)(D + 1) * kr0)
                 - hD2 * ((double)D * kr0);
        }
        float mean = (float)(num / (double)SEGLEN);
        if (coord) smY[s] = mean; else smX[s] = mean;
    }
    __syncthreads();

    if (t < 96) {
        int coord = t / NSEG, s = t % NSEG;
        int D = coord ? HEI : WID;
        const float* m = coord ? smY : smX;
        float start = m[SIDX_C];
        float dis = (float)(D / 2) - start;
        float a = rintf((m[s] - start) - dis);
        g_aligned[(b * NSEG + s) * 2 + coord] = (int)a;
    }
    if (t < NSTEP) {
        bool fx = outl(smX, SIDX_C + 1 + t);
        bool fy = outl(smY, SIDX_C + 1 + t);
        g_flags[b * NSTEP + t] = (fx || fy) ? 1 : 0;
    }
}

// ---------------- K3: per-row bitmaps (parallel) + zero cont ----------------
__global__ void __launch_bounds__(256) k_rowbits() {
    __shared__ unsigned bits[NWORD];
    int b = blockIdx.x / ROWS_USED, row = blockIdx.x % ROWS_USED;
    int t = threadIdx.x;

    for (int w = t; w < NWORD; w += 256) bits[w] = 0u;
    // zero this block's slice of cont
    {
        const int per = (HW + ROWS_USED - 1) / ROWS_USED;
        int base = row * per;
        int end = base + per; if (end > HW) end = HW;
        for (int p = base + t; p < end; p += 256) g_cont[(size_t)b * HW + p] = 0;
    }
    __syncthreads();

    const uint4* pk4 = (const uint4*)(g_packed + ((size_t)b * ROWS_USED + row) * SEGLEN);
    int s = row + SIDX_C;
    int ax = g_aligned[(b * NSEG + s) * 2];
    int ay = g_aligned[(b * NSEG + s) * 2 + 1];

    for (int g = t; g < SEGLEN / 4; g += 256) {
        uint4 v = pk4[g];
        unsigned vs[4] = {v.x, v.y, v.z, v.w};
        #pragma unroll
        for (int k = 0; k < 4; k++) {
            int x = (int)(vs[k] & 511u), y = (int)(vs[k] >> 9);
            int xx = min(max(x - ax, 0), WID - 1);
            int yy = min(max(y - ay, 0), HEI - 1);
            int p = yy * WID + xx;
            atomicOr(&bits[p >> 5], 1u << (p & 31));
        }
    }
    __syncthreads();

    unsigned* out = g_raw + (size_t)(b * ROWS_USED + row) * NWORD;
    for (int w = t; w < NWORD; w += 256) out[w] = bits[w];
}

// ---------------- K4: serial decisions + conf (bitmaps in registers) ----------------
// 800 threads; thread t owns words t, t+800, t+1600 (2400 words exactly).
__global__ void __launch_bounds__(800, 1) k_scanB() {
    __shared__ int s_red;
    int b = blockIdx.x, t = threadIdx.x;
    const unsigned* rawb = g_raw + (size_t)b * ROWS_USED * NWORD;

    unsigned v0[3], v1[3];
    unsigned c0[3], c1[3], c2[3], c3[3], c4[3], c5[3];
    int wi[3] = { t, t + 800, t + 1600 };

    #pragma unroll
    for (int j = 0; j < 3; j++) {
        v0[j] = rawb[wi[j]];
        v1[j] = 0xffffffffu;
        c0[j] = c1[j] = c2[j] = c3[j] = c4[j] = c5[j] = 0u;
    }

    if (t == 0) s_red = 0;
    if (t < ROWS_USED) g_applied[b * ROWS_USED + t] = (t == 0) ? 1 : 0;
    __syncthreads();

    {
        int lc = __popc(v0[0]) + __popc(v0[1]) + __popc(v0[2]);
        for (int o = 16; o; o >>= 1) lc += __shfl_down_sync(0xffffffffu, lc, o);
        if ((t & 31) == 0) atomicAdd(&s_red, lc);
    }
    __syncthreads();
    int cnt = s_red;

    for (int r = 1; r < ROWS_USED; r++) {
        if (g_flags[b * NSTEP + (r - 1)]) continue;   // inactive: no state change
        __syncthreads();                               // all reads of s_red done
        if (t == 0) s_red = 0;
        __syncthreads();

        unsigned rw[3];
        int nc = 0;
        #pragma unroll
        for (int j = 0; j < 3; j++) {
            rw[j] = rawb[(size_t)r * NWORD + wi[j]];
            // conf += raw & v0 & v1  (bit-plane ripple-carry add; conf <= 33 < 64)
            unsigned carry = rw[j] & v0[j] & v1[j];
            unsigned nx;
            nx = c0[j] & carry; c0[j] ^= carry; carry = nx;
            nx = c1[j] & carry; c1[j] ^= carry; carry = nx;
            nx = c2[j] & carry; c2[j] ^= carry; carry = nx;
            nx = c3[j] & carry; c3[j] ^= carry; carry = nx;
            nx = c4[j] & carry; c4[j] ^= carry; carry = nx;
            c5[j] ^= carry;
            nc += __popc(rw[j] & ~v0[j]);
        }
        for (int o = 16; o; o >>= 1) nc += __shfl_down_sync(0xffffffffu, nc, o);
        if ((t & 31) == 0) atomicAdd(&s_red, nc);
        __syncthreads();

        int newc = s_red;
        float ratio = (float)newc / (float)(cnt + newc);
        if (ratio < 0.01f) break;                     // stopped (conf already updated)

        if (t == 0) g_applied[b * ROWS_USED + r] = 1;
        #pragma unroll
        for (int j = 0; j < 3; j++) { v1[j] = v0[j]; v0[j] |= rw[j]; }
        cnt += newc;
    }

    // write conf image from bit-planes (coalesced: each thread writes 32 contiguous ints)
    #pragma unroll
    for (int j = 0; j < 3; j++) {
        int* dst = g_conf + (size_t)b * HW + wi[j] * 32;
        #pragma unroll
        for (int bit = 0; bit < 32; bit++) {
            int v =  (int)((c0[j] >> bit) & 1u)
                  | ((int)((c1[j] >> bit) & 1u) << 1)
                  | ((int)((c2[j] >> bit) & 1u) << 2)
                  | ((int)((c3[j] >> bit) & 1u) << 3)
                  | ((int)((c4[j] >> bit) & 1u) << 4)
                  | ((int)((c5[j] >> bit) & 1u) << 5);
            dst[bit] = v;
        }
    }
}

// ---------------- K5: container histogram for applied rows (parallel) ----------------
__global__ void __launch_bounds__(256) k_cont() {
    int b = blockIdx.x / ROWS_USED, row = blockIdx.x % ROWS_USED;
    if (!g_applied[b * ROWS_USED + row]) return;
    int t = threadIdx.x;

    const uint4* pk4 = (const uint4*)(g_packed + ((size_t)b * ROWS_USED + row) * SEGLEN);
    int s = row + SIDX_C;
    int ax = g_aligned[(b * NSEG + s) * 2];
    int ay = g_aligned[(b * NSEG + s) * 2 + 1];
    int* cont = g_cont + (size_t)b * HW;

    for (int g = t; g < SEGLEN / 4; g += 256) {
        uint4 v = pk4[g];
        unsigned vs[4] = {v.x, v.y, v.z, v.w};
        #pragma unroll
        for (int k = 0; k < 4; k++) {
            int x = (int)(vs[k] & 511u), y = (int)(vs[k] >> 9);
            int xx = min(max(x - ax, 0), WID - 1);
            int yy = min(max(y - ay, 0), HEI - 1);
            atomicAdd(&cont[yy * WID + xx], 1);
        }
    }
}

// ---------------- K6: normalize ----------------
__global__ void __launch_bounds__(512) k_norm(float* __restrict__ out) {
    __shared__ double s_sum, s_sq;
    int b = blockIdx.x >> 1, pass = blockIdx.x & 1;
    int t = threadIdx.x;
    const int* src = (pass ? g_conf : g_cont) + (size_t)b * HW;

    if (t == 0) { s_sum = 0.0; s_sq = 0.0; }
    __syncthreads();
    double ls = 0.0, lq = 0.0;
    for (int p = t; p < HW; p += 512) {
        double v = (double)src[p];
        ls += v; lq += v * v;
    }
    for (int o = 16; o; o >>= 1) {
        ls += __shfl_down_sync(0xffffffffu, ls, o);
        lq += __shfl_down_sync(0xffffffffu, lq, o);
    }
    if ((t & 31) == 0) { atomicAdd(&s_sum, ls); atomicAdd(&s_sq, lq); }
    __syncthreads();
    double n = (double)HW;
    double mu = s_sum / n;
    double var = (s_sq - s_sum * s_sum / n) / (n - 1.0);
    if (var < 0.0) var = 0.0;
    float clampv = (float)(mu + 3.0 * sqrt(var));
    float* op = out + ((size_t)b * 2 + pass) * HW;
    for (int p = t; p < HW; p += 512) {
        float v = (float)src[p];
        op[p] = fminf(v, clampv) / clampv;
    }
}

// ---------------- launch ----------------
extern "C" void kernel_launch(void* const* d_in, const int* in_sizes, int n_in,
                              void* d_out, int out_size) {
    const int*   ev   = (const int*)d_in[0];
    const float* kern = (const float*)d_in[1];
    float*       out  = (float*)d_out;
    (void)in_sizes; (void)n_in; (void)out_size;

    k_hist<<<NB * NSEG, 256>>>(ev);
    k_mean<<<NB, 128>>>(kern);
    k_rowbits<<<NB * ROWS_USED, 256>>>();
    k_scanB<<<NB, 800>>>();
    k_cont<<<NB * ROWS_USED, 256>>>();
    k_norm<<<NB * 2, 512>>>(out);
}